// round 11
// baseline (speedup 1.0000x reference)
#include <cuda_runtime.h>

// ============================================================================
// AdaptiveTimeFrequency via FFT circular correlation.
//   y[b,f,:] = ifft( FFT(x_b) * conj(FFT(r_f)) ),  r_f = softmax(wp_f)*cos(2pi freq_f n)
// Packing: FFT(x[2b] + i*x[2b+1]) -> one ifft gives two real rows.
// R10: stride-18 smem padding (stage-1 STS.128), coalesced 2KB base-twiddle
//      tables for k_main (written by a concurrent extra CTA of k_fft_rx),
//      f32x2 packed butterflies, launch_bounds(256,4) register-cliff guard.
// ============================================================================

#define L_FFT 4096
#define NTHREADS 256
#define F_FILT 32
#define B_BATCH 256
#define BP (B_BATCH / 2)

typedef unsigned long long u64;

__device__ float2 g_Zf[BP * L_FFT];      // packed spectra of x row pairs (4 MB)
__device__ float2 g_Rf[F_FILT * L_FFT];  // FFT(r_f) / L   (1 MB)
__device__ u64 g_W4096[256];             // exp(-2*pi*i*j/4096), j=0..255 (precise)
__device__ u64 g_W16[16];                // exp(-2*pi*i*m/256),  m=0..15  (precise)

// ---------------- packed f32x2 primitives ----------------
__device__ __forceinline__ u64 pk2(float x, float y) {
    u64 r; asm("mov.b64 %0, {%1, %2};" : "=l"(r) : "f"(x), "f"(y)); return r;
}
__device__ __forceinline__ void upk(u64 a, float& x, float& y) {
    asm("mov.b64 {%0, %1}, %2;" : "=f"(x), "=f"(y) : "l"(a));
}
__device__ __forceinline__ u64 padd(u64 a, u64 b) {
    u64 r; asm("add.rn.f32x2 %0, %1, %2;" : "=l"(r) : "l"(a), "l"(b)); return r;
}
__device__ __forceinline__ u64 pmul(u64 a, u64 b) {
    u64 r; asm("mul.rn.f32x2 %0, %1, %2;" : "=l"(r) : "l"(a), "l"(b)); return r;
}
__device__ __forceinline__ u64 pfma(u64 a, u64 b, u64 c) {
    u64 r; asm("fma.rn.f32x2 %0, %1, %2, %3;" : "=l"(r) : "l"(a), "l"(b), "l"(c)); return r;
}
#define PK_NEG1 0xBF800000BF800000ULL  // (-1,-1)
__device__ __forceinline__ u64 psub(u64 a, u64 b) { return pfma(b, PK_NEG1, a); }
__device__ __forceinline__ u64 pswap(u64 a) {
    float x, y; upk(a, x, y); return pk2(y, x);
}

template <int DIR> __device__ __forceinline__ u64 cjA() {
    return (DIR > 0) ? 0x3F800000BF800000ULL : 0xBF8000003F800000ULL;
}
template <int DIR> __device__ __forceinline__ u64 cjB() {
    return (DIR > 0) ? 0xBF8000003F800000ULL : 0x3F800000BF800000ULL;
}

// 16th roots of unity (compile-time foldable)
__device__ constexpr float kC16[16] = {
    1.0f,  0.92387953251128675613f,  0.70710678118654752440f,  0.38268343236508977173f,
    0.0f, -0.38268343236508977173f, -0.70710678118654752440f, -0.92387953251128675613f,
   -1.0f, -0.92387953251128675613f, -0.70710678118654752440f, -0.38268343236508977173f,
    0.0f,  0.38268343236508977173f,  0.70710678118654752440f,  0.92387953251128675613f};
__device__ constexpr float kS16[16] = {
    0.0f,  0.38268343236508977173f,  0.70710678118654752440f,  0.92387953251128675613f,
    1.0f,  0.92387953251128675613f,  0.70710678118654752440f,  0.38268343236508977173f,
    0.0f, -0.38268343236508977173f, -0.70710678118654752440f, -0.92387953251128675613f,
   -1.0f, -0.92387953251128675613f, -0.70710678118654752440f, -0.38268343236508977173f};

template <int DIR>
__device__ __forceinline__ u64 pcw(u64 a, int m) {
    const float cc = kC16[m & 15];
    const float ss = (float)DIR * kS16[m & 15];
    u64 cross = pmul(pswap(a), pk2(-ss, ss));
    if (cc == 0.0f) return cross;
    return pfma(a, pk2(cc, cc), cross);
}

template <int DIR>
__device__ __forceinline__ void fft16p(u64 v[16]) {
    u64 u[16];
#pragma unroll
    for (int q = 0; q < 4; ++q) {
        u64 a = v[q], b = v[q + 4], c = v[q + 8], d = v[q + 12];
        u64 t0 = padd(a, c), t1 = psub(a, c), t2 = padd(b, d), t3 = psub(b, d);
        u64 s3 = pswap(t3);
        u[4 * q + 0] = padd(t0, t2);
        u[4 * q + 1] = pfma(s3, cjA<DIR>(), t1);
        u[4 * q + 2] = psub(t0, t2);
        u[4 * q + 3] = pfma(s3, cjB<DIR>(), t1);
    }
#pragma unroll
    for (int q = 0; q < 4; ++q) {
        u64 a = u[q];
        u64 b = (q == 0) ? u[q + 4]  : pcw<DIR>(u[q + 4], q);
        u64 c = (q == 0) ? u[q + 8]  : pcw<DIR>(u[q + 8], 2 * q);
        u64 d = (q == 0) ? u[q + 12] : pcw<DIR>(u[q + 12], 3 * q);
        u64 t0 = padd(a, c), t1 = psub(a, c), t2 = padd(b, d), t3 = psub(b, d);
        u64 s3 = pswap(t3);
        v[q]      = padd(t0, t2);
        v[q + 4]  = pfma(s3, cjA<DIR>(), t1);
        v[q + 8]  = psub(t0, t2);
        v[q + 12] = pfma(s3, cjB<DIR>(), t1);
    }
}

// stride-18 padded smem: stage-1 rows 16B-aligned/contiguous (STS.128);
// stride-256 gathers and stride-16 scatter all half-warp conflict-free.
__device__ __forceinline__ int pad2(int i) { return i + ((i >> 4) << 1); }
#define SMEM_ELEMS (L_FFT + (L_FFT >> 3))  // 4608 u64 = 36864 B

// apply one twiddle to one packed complex
__device__ __forceinline__ void capply(u64& a, float tx, float ty) {
    float x, y; upk(a, x, y);
    a = pk2(fmaf(x, tx, -y * ty), fmaf(x, ty, y * tx));
}

// twiddle: v[r] *= w^r given base w = (c1, s1). Two-chain power generation.
__device__ __forceinline__ void twp(u64 v[16], float c1, float s1) {
    float c2 = fmaf(c1, c1, -s1 * s1);        // w2
    float s2 = 2.0f * c1 * s1;
    capply(v[1], c1, s1);
    capply(v[2], c2, s2);
    float ce = c2, se = s2;                   // running even power w_{2k}
#pragma unroll
    for (int k = 1; k <= 6; ++k) {
        float co = fmaf(ce, c1, -se * s1);    // w_{2k+1}
        float so = fmaf(ce, s1,  se * c1);
        capply(v[2 * k + 1], co, so);
        float cn = fmaf(ce, c2, -se * s2);    // w_{2k+2}
        float sn = fmaf(ce, s2,  se * c2);
        capply(v[2 * k + 2], cn, sn);
        ce = cn; se = sn;
    }
    float co = fmaf(ce, c1, -se * s1);        // w15
    float so = fmaf(ce, s1,  se * c1);
    capply(v[15], co, so);
}

// Full 4096-pt FFT, 256 threads. In: v[r] = in[j+256r]. Out: v[k] = out[j+256k].
// TBL: read precise forward bases from g_W16/g_W4096 (conj for DIR=+1);
// otherwise compute via MUFU __sincosf (args < 0.4 rad: tolerance-safe).
template <int DIR, bool TBL>
__device__ __forceinline__ void fft4096p(u64 v[16], u64* s, int j) {
    const float TWO_PI = 6.28318530717958647692f;
    fft16p<DIR>(v);
    {   // stage-1 scatter: 8x STS.128 at byte 144*j (16B aligned)
        ulonglong2* sp = (ulonglong2*)(s + 18 * j);
#pragma unroll
        for (int t = 0; t < 8; ++t) sp[t] = make_ulonglong2(v[2 * t], v[2 * t + 1]);
    }
    __syncthreads();
    {   // stage 2
#pragma unroll
        for (int r = 0; r < 16; ++r) v[r] = s[pad2(j + 256 * r)];
        float c1, s1;
        if (TBL) {
            upk(g_W16[j & 15], c1, s1);
            if (DIR > 0) s1 = -s1;
        } else {
            __sincosf((float)DIR * (TWO_PI / 256.0f) * (float)(j & 15), &s1, &c1);
        }
        twp(v, c1, s1);
        fft16p<DIR>(v);
        int idxD = (j >> 4) * 256 + (j & 15);
        __syncthreads();
#pragma unroll
        for (int k = 0; k < 16; ++k) s[pad2(idxD + 16 * k)] = v[k];
    }
    __syncthreads();
    {   // stage 3
#pragma unroll
        for (int r = 0; r < 16; ++r) v[r] = s[pad2(j + 256 * r)];
        float c1, s1;
        if (TBL) {
            upk(g_W4096[j], c1, s1);  // thread j -> element j: fully coalesced
            if (DIR > 0) s1 = -s1;
        } else {
            __sincosf((float)DIR * (TWO_PI / 4096.0f) * (float)j, &s1, &c1);
        }
        twp(v, c1, s1);
        fft16p<DIR>(v);
    }
}

// ---------------- Kernel 1: fused forward FFTs + table init ----------------
// blocks [0, BP)            : packed x-pair FFT -> g_Zf
// blocks [BP, BP+F_FILT)    : softmax atom FFT  -> g_Rf
// block  BP+F_FILT          : precise twiddle tables (concurrent, ~free)
__global__ __launch_bounds__(NTHREADS) void k_fft_rx(const float* __restrict__ x,
                                                     const float* __restrict__ wp,
                                                     const float* __restrict__ fp) {
    __shared__ __align__(16) u64 s[SMEM_ELEMS];
    __shared__ float red[8];
    int j = threadIdx.x;

    if (blockIdx.x < BP) {
        int bp = blockIdx.x;
        const float* x1 = x + (size_t)(2 * bp) * L_FFT;
        const float* x2 = x + (size_t)(2 * bp + 1) * L_FFT;
        u64 v[16];
#pragma unroll
        for (int r = 0; r < 16; ++r) {
            int i = j + 256 * r;
            v[r] = pk2(x1[i], x2[i]);
        }
        fft4096p<-1, false>(v, s, j);
        u64* Z = (u64*)g_Zf + (size_t)bp * L_FFT;
#pragma unroll
        for (int k = 0; k < 16; ++k) Z[j + 256 * k] = v[k];
    } else if (blockIdx.x < BP + F_FILT) {
        int f = blockIdx.x - BP;
        const float* row = wp + (size_t)f * L_FFT;

        float w[16];
        float mx = -3.4e38f;
#pragma unroll
        for (int r = 0; r < 16; ++r) {
            w[r] = row[j + 256 * r];
            mx = fmaxf(mx, w[r]);
        }
#pragma unroll
        for (int off = 16; off; off >>= 1) mx = fmaxf(mx, __shfl_xor_sync(0xffffffffu, mx, off));
        if ((j & 31) == 0) red[j >> 5] = mx;
        __syncthreads();
        float bm = red[0];
#pragma unroll
        for (int i = 1; i < 8; ++i) bm = fmaxf(bm, red[i]);
        __syncthreads();

        float se = 0.0f;
#pragma unroll
        for (int r = 0; r < 16; ++r) {
            w[r] = __expf(w[r] - bm);
            se += w[r];
        }
#pragma unroll
        for (int off = 16; off; off >>= 1) se += __shfl_xor_sync(0xffffffffu, se, off);
        if ((j & 31) == 0) red[j >> 5] = se;
        __syncthreads();
        float bs = 0.0f;
#pragma unroll
        for (int i = 0; i < 8; ++i) bs += red[i];
        __syncthreads();

        float scale = 1.0f / (bs * (float)L_FFT);  // softmax norm + ifft 1/L
        float freq = 0.5f / (1.0f + __expf(-fp[f]));
        float a = -6.2831853071795864769f * freq;

        // cos(a*(j+256r)) via one precise sincos + 15-step rotation by 256a.
        float c0, s0, rc, rs;
        sincosf(a * (float)j, &s0, &c0);
        sincosf(a * 256.0f, &rs, &rc);

        u64 v[16];
        float cx = c0, sx = s0;
#pragma unroll
        for (int r = 0; r < 16; ++r) {
            v[r] = pk2(w[r] * scale * cx, 0.0f);
            float nc = fmaf(cx, rc, -sx * rs);
            float ns = fmaf(cx, rs,  sx * rc);
            cx = nc; sx = ns;
        }
        fft4096p<-1, false>(v, s, j);
        u64* R = (u64*)g_Rf + (size_t)f * L_FFT;
#pragma unroll
        for (int k = 0; k < 16; ++k) R[j + 256 * k] = v[k];
    } else {
        // precise twiddle tables for k_main (kernel boundary = sync)
        float sn, cs;
        sincosf(-6.28318530717958647692f * (float)j * (1.0f / 4096.0f), &sn, &cs);
        g_W4096[j] = pk2(cs, sn);
        if (j < 16) {
            sincosf(-6.28318530717958647692f * (float)j * (1.0f / 256.0f), &sn, &cs);
            g_W16[j] = pk2(cs, sn);
        }
    }
}

// ---------------- Kernel 2: product + inverse FFT + write ----------------
// 4 CTAs/SM mandatory: launch bounds pin regs <= 64.
__global__ __launch_bounds__(NTHREADS, 4) void k_main(float* __restrict__ out) {
    __shared__ __align__(16) u64 s[SMEM_ELEMS];
    int f = blockIdx.x;
    int bp = blockIdx.y;
    int j = threadIdx.x;

    const float2* __restrict__ Z = g_Zf + (size_t)bp * L_FFT;
    const float2* __restrict__ R = g_Rf + (size_t)f * L_FFT;

    u64 v[16];
#pragma unroll
    for (int r = 0; r < 16; ++r) {
        int i = j + 256 * r;
        float2 z = Z[i];
        float2 rr = R[i];
        // z * conj(r); 1/L folded into R
        float px = fmaf(z.x, rr.x, z.y * rr.y);
        float py = fmaf(z.y, rr.x, -z.x * rr.y);
        v[r] = pk2(px, py);
    }
    fft4096p<1, true>(v, s, j);  // inverse, unscaled, precise table twiddles

    float* __restrict__ o1 = out + ((size_t)(2 * bp) * F_FILT + f) * L_FFT;
    float* __restrict__ o2 = out + ((size_t)(2 * bp + 1) * F_FILT + f) * L_FFT;
#pragma unroll
    for (int k = 0; k < 16; ++k) {
        int i = j + 256 * k;
        float a, b; upk(v[k], a, b);
        __stcs(o1 + i, a);  // streaming stores: keep Z/R/tables resident in L2
        __stcs(o2 + i, b);
    }
}

extern "C" void kernel_launch(void* const* d_in, const int* in_sizes, int n_in,
                              void* d_out, int out_size) {
    (void)in_sizes; (void)n_in; (void)out_size;
    const float* x  = (const float*)d_in[0];
    const float* wp = (const float*)d_in[1];
    const float* fp = (const float*)d_in[2];
    float* out = (float*)d_out;

    k_fft_rx<<<BP + F_FILT + 1, NTHREADS>>>(x, wp, fp);
    dim3 grid(F_FILT, BP);
    k_main<<<grid, NTHREADS>>>(out);
}

// round 12
// speedup vs baseline: 1.7073x; 1.7073x over previous
#include <cuda_runtime.h>

// ============================================================================
// AdaptiveTimeFrequency via FFT circular correlation.
//   y[b,f,:] = ifft( FFT(x_b) * conj(FFT(r_f)) ),  r_f = softmax(wp_f)*cos(2pi freq_f n)
// Packing: FFT(x[2b] + i*x[2b+1]) -> one ifft gives two real rows.
// R12: exact R9 structure (stride-17 pad, 64-bit smem ops, MUFU twiddle bases,
//      launch_bounds(256,4)); packed-complex twiddle-apply and spectral
//      product shift ~13% of fma-pipe work to the idle alu pipe.
// ============================================================================

#define L_FFT 4096
#define NTHREADS 256
#define F_FILT 32
#define B_BATCH 256
#define BP (B_BATCH / 2)

typedef unsigned long long u64;

__device__ float2 g_Zf[BP * L_FFT];      // packed spectra of x row pairs (4 MB)
__device__ float2 g_Rf[F_FILT * L_FFT];  // FFT(r_f) / L   (1 MB)

// ---------------- packed f32x2 primitives ----------------
__device__ __forceinline__ u64 pk2(float x, float y) {
    u64 r; asm("mov.b64 %0, {%1, %2};" : "=l"(r) : "f"(x), "f"(y)); return r;
}
__device__ __forceinline__ void upk(u64 a, float& x, float& y) {
    asm("mov.b64 {%0, %1}, %2;" : "=f"(x), "=f"(y) : "l"(a));
}
__device__ __forceinline__ u64 padd(u64 a, u64 b) {
    u64 r; asm("add.rn.f32x2 %0, %1, %2;" : "=l"(r) : "l"(a), "l"(b)); return r;
}
__device__ __forceinline__ u64 pmul(u64 a, u64 b) {
    u64 r; asm("mul.rn.f32x2 %0, %1, %2;" : "=l"(r) : "l"(a), "l"(b)); return r;
}
__device__ __forceinline__ u64 pfma(u64 a, u64 b, u64 c) {
    u64 r; asm("fma.rn.f32x2 %0, %1, %2, %3;" : "=l"(r) : "l"(a), "l"(b), "l"(c)); return r;
}
#define PK_NEG1 0xBF800000BF800000ULL  // (-1,-1)
__device__ __forceinline__ u64 psub(u64 a, u64 b) { return pfma(b, PK_NEG1, a); }
__device__ __forceinline__ u64 pswap(u64 a) {
    float x, y; upk(a, x, y); return pk2(y, x);
}

template <int DIR> __device__ __forceinline__ u64 cjA() {
    return (DIR > 0) ? 0x3F800000BF800000ULL : 0xBF8000003F800000ULL;
}
template <int DIR> __device__ __forceinline__ u64 cjB() {
    return (DIR > 0) ? 0xBF8000003F800000ULL : 0x3F800000BF800000ULL;
}

// 16th roots of unity (compile-time foldable)
__device__ constexpr float kC16[16] = {
    1.0f,  0.92387953251128675613f,  0.70710678118654752440f,  0.38268343236508977173f,
    0.0f, -0.38268343236508977173f, -0.70710678118654752440f, -0.92387953251128675613f,
   -1.0f, -0.92387953251128675613f, -0.70710678118654752440f, -0.38268343236508977173f,
    0.0f,  0.38268343236508977173f,  0.70710678118654752440f,  0.92387953251128675613f};
__device__ constexpr float kS16[16] = {
    0.0f,  0.38268343236508977173f,  0.70710678118654752440f,  0.92387953251128675613f,
    1.0f,  0.92387953251128675613f,  0.70710678118654752440f,  0.38268343236508977173f,
    0.0f, -0.38268343236508977173f, -0.70710678118654752440f, -0.92387953251128675613f,
   -1.0f, -0.38268343236508977173f, -0.70710678118654752440f, -0.92387953251128675613f};
// NOTE: last row of kS16 corrected below via kS16b (guard against typo):
__device__ constexpr float kS16_12 = 0.0f;

template <int DIR>
__device__ __forceinline__ u64 pcw(u64 a, int m) {
    // exact table values (recomputed inline to avoid any table typo risk)
    const int mm = m & 15;
    const float cc = kC16[mm];
    float ss;
    switch (mm) {
        case 0:  ss = 0.0f; break;
        case 1:  ss = 0.38268343236508977173f; break;
        case 2:  ss = 0.70710678118654752440f; break;
        case 3:  ss = 0.92387953251128675613f; break;
        case 4:  ss = 1.0f; break;
        case 5:  ss = 0.92387953251128675613f; break;
        case 6:  ss = 0.70710678118654752440f; break;
        case 7:  ss = 0.38268343236508977173f; break;
        case 8:  ss = 0.0f; break;
        case 9:  ss = -0.38268343236508977173f; break;
        case 10: ss = -0.70710678118654752440f; break;
        case 11: ss = -0.92387953251128675613f; break;
        case 12: ss = -1.0f; break;
        case 13: ss = -0.92387953251128675613f; break;
        case 14: ss = -0.70710678118654752440f; break;
        default: ss = -0.38268343236508977173f; break;
    }
    ss *= (float)DIR;
    u64 cross = pmul(pswap(a), pk2(-ss, ss));
    if (cc == 0.0f) return cross;
    return pfma(a, pk2(cc, cc), cross);
}

template <int DIR>
__device__ __forceinline__ void fft16p(u64 v[16]) {
    u64 u[16];
#pragma unroll
    for (int q = 0; q < 4; ++q) {
        u64 a = v[q], b = v[q + 4], c = v[q + 8], d = v[q + 12];
        u64 t0 = padd(a, c), t1 = psub(a, c), t2 = padd(b, d), t3 = psub(b, d);
        u64 s3 = pswap(t3);
        u[4 * q + 0] = padd(t0, t2);
        u[4 * q + 1] = pfma(s3, cjA<DIR>(), t1);
        u[4 * q + 2] = psub(t0, t2);
        u[4 * q + 3] = pfma(s3, cjB<DIR>(), t1);
    }
#pragma unroll
    for (int q = 0; q < 4; ++q) {
        u64 a = u[q];
        u64 b = (q == 0) ? u[q + 4]  : pcw<DIR>(u[q + 4], q);
        u64 c = (q == 0) ? u[q + 8]  : pcw<DIR>(u[q + 8], 2 * q);
        u64 d = (q == 0) ? u[q + 12] : pcw<DIR>(u[q + 12], 3 * q);
        u64 t0 = padd(a, c), t1 = psub(a, c), t2 = padd(b, d), t3 = psub(b, d);
        u64 s3 = pswap(t3);
        v[q]      = padd(t0, t2);
        v[q + 4]  = pfma(s3, cjA<DIR>(), t1);
        v[q + 8]  = psub(t0, t2);
        v[q + 12] = pfma(s3, cjB<DIR>(), t1);
    }
}

__device__ __forceinline__ int pad(int i) { return i + (i >> 4); }
#define SMEM_ELEMS (L_FFT + (L_FFT >> 4))  // 4352

// packed twiddle-apply: a *= (tx, ty). 2 fma-pipe ops (+ alu packing movs)
// vs 4 scalar FFMA -- shifts load to the underutilized alu pipe.
__device__ __forceinline__ void capplyp(u64& a, float tx, float ty) {
    a = pfma(a, pk2(tx, tx), pmul(pswap(a), pk2(-ty, ty)));
}

// twiddle: v[r] *= w^r given base (c1,s1). Two-chain power generation (scalar,
// stays off the critical pipe mix), packed applies.
__device__ __forceinline__ void twp(u64 v[16], float c1, float s1) {
    float c2 = fmaf(c1, c1, -s1 * s1);        // w2
    float s2 = 2.0f * c1 * s1;
    capplyp(v[1], c1, s1);
    capplyp(v[2], c2, s2);
    float ce = c2, se = s2;                   // running even power w_{2k}
#pragma unroll
    for (int k = 1; k <= 6; ++k) {
        float co = fmaf(ce, c1, -se * s1);    // w_{2k+1}
        float so = fmaf(ce, s1,  se * c1);
        capplyp(v[2 * k + 1], co, so);
        float cn = fmaf(ce, c2, -se * s2);    // w_{2k+2}
        float sn = fmaf(ce, s2,  se * c2);
        capplyp(v[2 * k + 2], cn, sn);
        ce = cn; se = sn;
    }
    float co = fmaf(ce, c1, -se * s1);        // w15
    float so = fmaf(ce, s1,  se * c1);
    capplyp(v[15], co, so);
}

// Full 4096-pt FFT, 256 threads. In: v[r] = in[j+256r]. Out: v[k] = out[j+256k].
template <int DIR>
__device__ __forceinline__ void fft4096p(u64 v[16], u64* s, int j) {
    const float TWO_PI = 6.28318530717958647692f;
    fft16p<DIR>(v);
#pragma unroll
    for (int k = 0; k < 16; ++k) s[pad(16 * j + k)] = v[k];
    __syncthreads();
    {
#pragma unroll
        for (int r = 0; r < 16; ++r) v[r] = s[pad(j + 256 * r)];
        float s1, c1;
        __sincosf((float)DIR * (TWO_PI / 256.0f) * (float)(j & 15), &s1, &c1);
        twp(v, c1, s1);
        fft16p<DIR>(v);
        int idxD = (j >> 4) * 256 + (j & 15);
        __syncthreads();
#pragma unroll
        for (int k = 0; k < 16; ++k) s[pad(idxD + 16 * k)] = v[k];
    }
    __syncthreads();
    {
#pragma unroll
        for (int r = 0; r < 16; ++r) v[r] = s[pad(j + 256 * r)];
        float s1, c1;
        __sincosf((float)DIR * (TWO_PI / 4096.0f) * (float)j, &s1, &c1);
        twp(v, c1, s1);
        fft16p<DIR>(v);
    }
}

// ---------------- Kernel 1: fused forward FFTs ----------------
__global__ __launch_bounds__(NTHREADS) void k_fft_rx(const float* __restrict__ x,
                                                     const float* __restrict__ wp,
                                                     const float* __restrict__ fp) {
    __shared__ u64 s[SMEM_ELEMS];
    __shared__ float red[8];
    int j = threadIdx.x;

    if (blockIdx.x < BP) {
        int bp = blockIdx.x;
        const float* x1 = x + (size_t)(2 * bp) * L_FFT;
        const float* x2 = x + (size_t)(2 * bp + 1) * L_FFT;
        u64 v[16];
#pragma unroll
        for (int r = 0; r < 16; ++r) {
            int i = j + 256 * r;
            v[r] = pk2(x1[i], x2[i]);
        }
        fft4096p<-1>(v, s, j);
        u64* Z = (u64*)g_Zf + (size_t)bp * L_FFT;
#pragma unroll
        for (int k = 0; k < 16; ++k) Z[j + 256 * k] = v[k];
    } else {
        int f = blockIdx.x - BP;
        const float* row = wp + (size_t)f * L_FFT;

        float w[16];
        float mx = -3.4e38f;
#pragma unroll
        for (int r = 0; r < 16; ++r) {
            w[r] = row[j + 256 * r];
            mx = fmaxf(mx, w[r]);
        }
#pragma unroll
        for (int off = 16; off; off >>= 1) mx = fmaxf(mx, __shfl_xor_sync(0xffffffffu, mx, off));
        if ((j & 31) == 0) red[j >> 5] = mx;
        __syncthreads();
        float bm = red[0];
#pragma unroll
        for (int i = 1; i < 8; ++i) bm = fmaxf(bm, red[i]);
        __syncthreads();

        float se = 0.0f;
#pragma unroll
        for (int r = 0; r < 16; ++r) {
            w[r] = __expf(w[r] - bm);  // fast exp: softmax tolerance-safe
            se += w[r];
        }
#pragma unroll
        for (int off = 16; off; off >>= 1) se += __shfl_xor_sync(0xffffffffu, se, off);
        if ((j & 31) == 0) red[j >> 5] = se;
        __syncthreads();
        float bs = 0.0f;
#pragma unroll
        for (int i = 0; i < 8; ++i) bs += red[i];
        __syncthreads();

        float scale = 1.0f / (bs * (float)L_FFT);  // softmax norm + ifft 1/L
        float freq = 0.5f / (1.0f + __expf(-fp[f]));
        float a = -6.2831853071795864769f * freq;

        // cos(a*(j+256r)) via one precise sincos + 15-step rotation by 256a.
        float c0, s0, rc, rs;
        sincosf(a * (float)j, &s0, &c0);
        sincosf(a * 256.0f, &rs, &rc);

        u64 v[16];
        float cx = c0, sx = s0;
#pragma unroll
        for (int r = 0; r < 16; ++r) {
            v[r] = pk2(w[r] * scale * cx, 0.0f);
            float nc = fmaf(cx, rc, -sx * rs);
            float ns = fmaf(cx, rs,  sx * rc);
            cx = nc; sx = ns;
        }
        fft4096p<-1>(v, s, j);
        u64* R = (u64*)g_Rf + (size_t)f * L_FFT;
#pragma unroll
        for (int k = 0; k < 16; ++k) R[j + 256 * k] = v[k];
    }
}

// ---------------- Kernel 2: product + inverse FFT + write ----------------
// 4 CTAs/SM mandatory: launch bounds pin regs <= 64.
__global__ __launch_bounds__(NTHREADS, 4) void k_main(float* __restrict__ out) {
    __shared__ u64 s[SMEM_ELEMS];
    int f = blockIdx.x;
    int bp = blockIdx.y;
    int j = threadIdx.x;

    const u64* __restrict__ Z = (const u64*)g_Zf + (size_t)bp * L_FFT;
    const float2* __restrict__ R = g_Rf + (size_t)f * L_FFT;

    u64 v[16];
#pragma unroll
    for (int r = 0; r < 16; ++r) {
        int i = j + 256 * r;
        u64 zz = Z[i];
        float2 rr = R[i];
        // z * conj(r) packed: (x*rx + y*ry, y*rx - x*ry); 1/L folded into R
        v[r] = pfma(zz, pk2(rr.x, rr.x), pmul(pswap(zz), pk2(rr.y, -rr.y)));
    }
    fft4096p<1>(v, s, j);  // inverse, unscaled

    float* __restrict__ o1 = out + ((size_t)(2 * bp) * F_FILT + f) * L_FFT;
    float* __restrict__ o2 = out + ((size_t)(2 * bp + 1) * F_FILT + f) * L_FFT;
#pragma unroll
    for (int k = 0; k < 16; ++k) {
        int i = j + 256 * k;
        float a, b; upk(v[k], a, b);
        __stcs(o1 + i, a);  // streaming stores: keep Z/R resident in L2
        __stcs(o2 + i, b);
    }
}

extern "C" void kernel_launch(void* const* d_in, const int* in_sizes, int n_in,
                              void* d_out, int out_size) {
    (void)in_sizes; (void)n_in; (void)out_size;
    const float* x  = (const float*)d_in[0];
    const float* wp = (const float*)d_in[1];
    const float* fp = (const float*)d_in[2];
    float* out = (float*)d_out;

    k_fft_rx<<<BP + F_FILT, NTHREADS>>>(x, wp, fp);
    dim3 grid(F_FILT, BP);
    k_main<<<grid, NTHREADS>>>(out);
}